// round 15
// baseline (speedup 1.0000x reference)
#include <cuda_runtime.h>
#include <cuda_bf16.h>

// out[b,0,h,w] = sum_c x[b,c,h,w] * wq[c] + bias
// x: (8,128,512,512) f32, W: 128 f32 (quant-dequant to int8 grid), b: 1 f32
// Pure HBM-bound streaming reduction over channel dim.
// R3:  172.8us @ DRAM 80.3% (2048 blocks, ~2 waves).
// R6:  166.2us @ DRAM 84.8% (1024 blocks, regs=42 -> ragged wave).
// R9:  159.8us @ DRAM 85.8% (fused quant, smem weights, 36-reg single wave).
// R11: 189.3us REGRESSION — shfl in hot loop throttled LDG issue. Reverted.
// R12: 158.2us @ DRAM 84.6% (__ldcs/__stcs).
// R13: 156.4us @ DRAM 84.3% (barrier-free per-warp weight quant).
// R14: work-steal the second 1024 tiles to absorb L2-die finish-time spread.
//      Ticket counter needs NO reset: every launch consumes exactly 2048
//      increments (1024 process + 1 stop per block), so (ticket & 2047) is
//      launch-relative. Deterministic output, graph-safe, alloc-free.

#define C_CH   128
#define HW     (512 * 512)        // 262144 elems per plane
#define HW4    (HW / 4)           // 65536 float4 per plane
#define BATCH  8
#define NBLK   1024               // <= 1064 (=152 SMs * 7 blocks) -> one wave
#define NTILES 2048               // 524288 float4 outputs / 256 threads
#define NWARP  8
#define FULLM  0xffffffffu

__device__ unsigned g_ticket = 0;  // monotonic; wraps mod 2^32 (2048 | 2^32)

__device__ __forceinline__ void process_tile(
    int tile, int t, const float* ws_row, float bb,
    const float* __restrict__ x, float* __restrict__ out)
{
    int o4 = tile * 256 + t;                  // 0..524287
    int b  = o4 >> 16;                        // o4 / HW4
    int s4 = o4 & (HW4 - 1);                  // o4 % HW4

    const float4* xp = reinterpret_cast<const float4*>(x)
                     + (size_t)b * (C_CH * HW4) + s4;

    float ax0 = 0.f, ay0 = 0.f, az0 = 0.f, aw0 = 0.f;
    float ax1 = 0.f, ay1 = 0.f, az1 = 0.f, aw1 = 0.f;

    #pragma unroll 8
    for (int c = 0; c < C_CH / 2; ++c) {
        float4 v0 = __ldcs(xp + (size_t)c * HW4);            // evict-first
        float4 v1 = __ldcs(xp + (size_t)(c + C_CH / 2) * HW4);
        float w0 = ws_row[c];                                // broadcast LDS
        float w1 = ws_row[c + C_CH / 2];
        ax0 = fmaf(v0.x, w0, ax0);
        ay0 = fmaf(v0.y, w0, ay0);
        az0 = fmaf(v0.z, w0, az0);
        aw0 = fmaf(v0.w, w0, aw0);
        ax1 = fmaf(v1.x, w1, ax1);
        ay1 = fmaf(v1.y, w1, ay1);
        az1 = fmaf(v1.z, w1, az1);
        aw1 = fmaf(v1.w, w1, aw1);
    }

    float4 r;
    r.x = ax0 + ax1 + bb;
    r.y = ay0 + ay1 + bb;
    r.z = az0 + az1 + bb;
    r.w = aw0 + aw1 + bb;
    __stcs(reinterpret_cast<float4*>(out) + o4, r);
}

__global__ __launch_bounds__(256, 7) void channel_reduce_fused_kernel(
    const float* __restrict__ x,
    const float* __restrict__ W,
    const float* __restrict__ bias,
    float* __restrict__ out)
{
    // Per-warp private dequantized weights: zero cross-warp sync.
    __shared__ float ws[NWARP][C_CH];
    __shared__ int  s_tile;                   // stolen-tile broadcast

    int t    = threadIdx.x;
    int wid  = t >> 5;
    int lane = t & 31;

    float bb = bias[0];

    // --- warp-local quant-dequant (no barriers): lane l owns channels 4l..4l+3
    float4 wv = reinterpret_cast<const float4*>(W)[lane];   // 32 lanes x 4 = 128
    float m = fmaxf(fmaxf(fabsf(wv.x), fabsf(wv.y)),
                    fmaxf(fabsf(wv.z), fabsf(wv.w)));
    #pragma unroll
    for (int s = 16; s > 0; s >>= 1)
        m = fmaxf(m, __shfl_xor_sync(FULLM, m, s));
    float scale = m / 127.0f;
    float inv   = 127.0f / m;
    float4 q;
    q.x = fminf(fmaxf(rintf(wv.x * inv), -127.0f), 127.0f) * scale;
    q.y = fminf(fmaxf(rintf(wv.y * inv), -127.0f), 127.0f) * scale;
    q.z = fminf(fmaxf(rintf(wv.z * inv), -127.0f), 127.0f) * scale;
    q.w = fminf(fmaxf(rintf(wv.w * inv), -127.0f), 127.0f) * scale;
    reinterpret_cast<float4*>(ws[wid])[lane] = q;           // STS.128, own warp
    __syncwarp();

    // --- static tile: blockIdx (tiles 0..1023), starts streaming immediately
    process_tile((int)blockIdx.x, t, ws[wid], bb, x, out);

    // --- steal tiles 1024..2047. Per launch: exactly 1024 process tickets +
    //     1024 stop tickets (one per block) = 2048 increments total, so the
    //     launch window is always 2048-aligned and (ticket & 2047) is the
    //     launch-relative position. No counter reset required.
    for (;;) {
        __syncthreads();                      // all threads done with prev tile
        if (t == 0) {
            unsigned idx = atomicAdd(&g_ticket, 1u) & (NTILES - 1u);
            s_tile = (idx < (unsigned)NBLK) ? (int)(NBLK + idx) : -1;
        }
        __syncthreads();
        int tile = s_tile;
        if (tile < 0) break;
        process_tile(tile, t, ws[wid], bb, x, out);
    }
}

extern "C" void kernel_launch(void* const* d_in, const int* in_sizes, int n_in,
                              void* d_out, int out_size) {
    const float* x    = (const float*)d_in[0];
    const float* W    = (const float*)d_in[1];
    const float* bias = (const float*)d_in[2];
    float* out        = (float*)d_out;

    channel_reduce_fused_kernel<<<NBLK, 256>>>(x, W, bias, out);
}